// round 12
// baseline (speedup 1.0000x reference)
#include <cuda_runtime.h>
#include <cuda_bf16.h>
#include <cstdint>

#define N_NODES  8000
#define N_EDGES  32000
#define N_GRAPHS 32

// ---------------- scratch (device globals; no allocations anywhere) --------
__device__ float g_h1[N_NODES * 8];
__device__ float g_h2[N_NODES * 64];
// one contiguous zeroed region: agg1 | agg2 | agg3 | pool
__device__ float g_aggz[N_NODES * 200 + N_GRAPHS * 128];
// bf16 B-fragments of w2, per-lane contiguous layout:
// uint4 index = ((og*IN + i)*32 + lane)*2 + q
__device__ uint4 g_bf_l3[16 * 64 * 32 * 2];
__device__ uint4 g_bf_l2[8 * 8 * 32 * 2];
__device__ uint4 g_bf_l1[4 * 1 * 32 * 2];

__device__ __forceinline__ float leaky(float v) { return fmaxf(v, 0.1f * v); }

__device__ __forceinline__ uint32_t pack_bf2(float x, float y) {
    __nv_bfloat16 bx = __float2bfloat16(x);
    __nv_bfloat16 by = __float2bfloat16(y);
    uint16_t ux = *(uint16_t*)&bx, uy = *(uint16_t*)&by;
    return (uint32_t)ux | ((uint32_t)uy << 16);
}

// mma.sync m16n8k16 row.col f32 += bf16*bf16 (accumulate in place)
__device__ __forceinline__ void mma_acc(float* d, const uint32_t* a,
                                        uint32_t b0, uint32_t b1) {
    asm volatile(
        "mma.sync.aligned.m16n8k16.row.col.f32.bf16.bf16.f32 "
        "{%0,%1,%2,%3}, {%4,%5,%6,%7}, {%8,%9}, {%0,%1,%2,%3};"
        : "+f"(d[0]), "+f"(d[1]), "+f"(d[2]), "+f"(d[3])
        : "r"(a[0]), "r"(a[1]), "r"(a[2]), "r"(a[3]), "r"(b0), "r"(b1));
}

// ---------------- prep body: one uint4 fragment of w2 ----------------------
__device__ __forceinline__ void prep_one(const float* __restrict__ w2,
                                         uint4* __restrict__ frag,
                                         int IN, int OUT, int idx)
{
    int q    = idx & 1;
    int lane = (idx >> 1) & 31;
    int i    = (idx >> 6) % IN;
    int og   = idx / (IN * 64);
    int t4 = lane & 3, g = lane >> 2;
    int ncols = IN * OUT;
    int col = i * OUT + og * 8 + g;

    uint32_t r[4];
#pragma unroll
    for (int kk = 0; kk < 2; kk++) {
        int kt = q * 2 + kk;
        int k0 = kt * 16 + t4 * 2;
        r[kk * 2 + 0] = pack_bf2(w2[(k0    ) * ncols + col], w2[(k0 + 1) * ncols + col]);
        r[kk * 2 + 1] = pack_bf2(w2[(k0 + 8) * ncols + col], w2[(k0 + 9) * ncols + col]);
    }
    frag[idx] = make_uint4(r[0], r[1], r[2], r[3]);
}

// ---------------- setup: zero accumulators + build ALL fragments, 1 launch --
__global__ void setup_kernel(float4* __restrict__ aggz4, int nz4,
                             const float* __restrict__ w2_3, uint4* __restrict__ bf3,
                             const float* __restrict__ w2_2, uint4* __restrict__ bf2,
                             const float* __restrict__ w2_1, uint4* __restrict__ bf1)
{
    int gid = blockIdx.x * blockDim.x + threadIdx.x;
    if (gid < nz4) aggz4[gid] = make_float4(0.f, 0.f, 0.f, 0.f);
    if (gid < 65536) {
        prep_one(w2_3, bf3, 64, 128, gid);
    } else if (gid < 65536 + 4096) {
        prep_one(w2_2, bf2, 8, 64, gid - 65536);
    } else if (gid < 65536 + 4096 + 256) {
        prep_one(w2_1, bf1, 1, 32, gid - 65536 - 4096);
    }
}

// ---------------- fused NNConv via bf16 mma.sync (layers 2 & 3) -------------
// Block = 128 edges, 128 threads = 4 warps, 32 edges/warp (TWO M16 tiles).
// b2 staged in smem; D zero-init; bias added in epilogue (round-9 structure).
template <int IN, int OUT>
__global__ __launch_bounds__(128)
void edge_conv_mma(const float* __restrict__ x,
                   const float* __restrict__ h,
                   const int*   __restrict__ ei,
                   const float* __restrict__ w1,
                   const float* __restrict__ b1,
                   const uint4* __restrict__ bfrag,
                   const float* __restrict__ b2,
                   float*       __restrict__ agg)
{
    constexpr int OG = OUT / 8;
    constexpr int W_EHI  = 0;                    // 128 x 33 bf16x2 words
    constexpr int W_H    = W_EHI + 128 * 33;     // IN x 128 fp32
    constexpr int W_B2   = W_H + IN * 128;       // IN*OUT fp32
    constexpr int W_ATTR = W_B2 + IN * OUT;      // 384
    constexpr int W_SRC  = W_ATTR + 384;
    constexpr int W_DST  = W_SRC + 128;

    extern __shared__ uint32_t sm[];
    uint32_t* e_hi   = sm + W_EHI;
    float*    h_s    = (float*)(sm + W_H);
    float*    b2_s   = (float*)(sm + W_B2);
    float*    attr_s = (float*)(sm + W_ATTR);
    int*      src_s  = (int*)(sm + W_SRC);
    int*      dst_s  = (int*)(sm + W_DST);

    const int tid = threadIdx.x;
    const int e0  = blockIdx.x * 128;

    // --- edge indices + relative-position attrs
    {
        int j = tid;
        int s = ei[e0 + j];
        int d = ei[N_EDGES + e0 + j];
        src_s[j] = s; dst_s[j] = d;
        attr_s[j * 3 + 0] = x[d * 4 + 1] - x[s * 4 + 1];
        attr_s[j * 3 + 1] = x[d * 4 + 2] - x[s * 4 + 2];
        attr_s[j * 3 + 2] = x[d * 4 + 3] - x[s * 4 + 3];
    }
    // --- stage b2
    for (int idx = tid; idx < IN * OUT / 4; idx += 128)
        ((float4*)b2_s)[idx] = ((const float4*)b2)[idx];
    __syncthreads();

    // --- edge hidden e = leaky(attr @ w1 + b1), packed bf16x2
    for (int idx = tid; idx < 4096; idx += 128) {
        int row = idx >> 5, cp = idx & 31;
        float a0 = attr_s[row * 3], a1 = attr_s[row * 3 + 1], a2 = attr_s[row * 3 + 2];
        int c0 = cp * 2, c1 = c0 + 1;
        float v0 = leaky(b1[c0] + a0 * w1[c0] + a1 * w1[64 + c0] + a2 * w1[128 + c0]);
        float v1 = leaky(b1[c1] + a0 * w1[c1] + a1 * w1[64 + c1] + a2 * w1[128 + c1]);
        e_hi[row * 33 + cp] = pack_bf2(v0, v1);
    }
    // --- h[src] gathered transposed: h_s[i*128 + j]
    for (int idx = tid; idx < 128 * (IN / 4); idx += 128) {
        int j = idx & 127, q = idx >> 7;
        float4 v = ((const float4*)(h + src_s[j] * IN))[q];
        h_s[(4 * q + 0) * 128 + j] = v.x;
        h_s[(4 * q + 1) * 128 + j] = v.y;
        h_s[(4 * q + 2) * 128 + j] = v.z;
        h_s[(4 * q + 3) * 128 + j] = v.w;
    }
    __syncthreads();

    const int lane = tid & 31, w = tid >> 5;
    const int g = lane >> 2, t4 = lane & 3;
    const int r0 = w * 32 + g;            // tile0 rows: r0, r0+8
    const int r2 = r0 + 16;               // tile1 rows: r2, r2+8

    // --- A fragments for both tiles (built once)
    uint32_t aF0[4][4], aF1[4][4];
#pragma unroll
    for (int kt = 0; kt < 4; kt++) {
        int cp = kt * 8 + t4;
        aF0[kt][0] = e_hi[(r0    ) * 33 + cp];
        aF0[kt][1] = e_hi[(r0 + 8) * 33 + cp];
        aF0[kt][2] = e_hi[(r0    ) * 33 + cp + 4];
        aF0[kt][3] = e_hi[(r0 + 8) * 33 + cp + 4];
        aF1[kt][0] = e_hi[(r2    ) * 33 + cp];
        aF1[kt][1] = e_hi[(r2 + 8) * 33 + cp];
        aF1[kt][2] = e_hi[(r2    ) * 33 + cp + 4];
        aF1[kt][3] = e_hi[(r2 + 8) * 33 + cp + 4];
    }

    const int d0n = dst_s[r0], d1n = dst_s[r0 + 8];
    const int d2n = dst_s[r2], d3n = dst_s[r2 + 8];

    for (int og2 = 0; og2 < OG / 2; og2++) {
        const int ogA = og2 * 2, ogB = ogA + 1;
        const uint4* pA = bfrag + ((size_t)(ogA * IN) * 32 + lane) * 2;
        const uint4* pB = bfrag + ((size_t)(ogB * IN) * 32 + lane) * 2;
        const int bcA = ogA * 8 + t4 * 2;
        const int bcB = ogB * 8 + t4 * 2;

        float acA0[4] = {0,0,0,0}, acB0[4] = {0,0,0,0};
        float acA1[4] = {0,0,0,0}, acB1[4] = {0,0,0,0};

        uint4 cA0 = pA[0], cA1 = pA[1];
        uint4 cB0 = pB[0], cB1 = pB[1];

#pragma unroll 2
        for (int i = 0; i < IN; i++) {
            uint4 nA0, nA1, nB0, nB1;
            if (i + 1 < IN) {
                const uint4* qA = pA + (size_t)(i + 1) * 64;
                const uint4* qB = pB + (size_t)(i + 1) * 64;
                nA0 = qA[0]; nA1 = qA[1];
                nB0 = qB[0]; nB1 = qB[1];
            }

            float dA0[4] = {0,0,0,0}, dB0[4] = {0,0,0,0};
            float dA1[4] = {0,0,0,0}, dB1[4] = {0,0,0,0};
            // 4 independent chains of 4, interleaved
            mma_acc(dA0, aF0[0], cA0.x, cA0.y);
            mma_acc(dB0, aF0[0], cB0.x, cB0.y);
            mma_acc(dA1, aF1[0], cA0.x, cA0.y);
            mma_acc(dB1, aF1[0], cB0.x, cB0.y);
            mma_acc(dA0, aF0[1], cA0.z, cA0.w);
            mma_acc(dB0, aF0[1], cB0.z, cB0.w);
            mma_acc(dA1, aF1[1], cA0.z, cA0.w);
            mma_acc(dB1, aF1[1], cB0.z, cB0.w);
            mma_acc(dA0, aF0[2], cA1.x, cA1.y);
            mma_acc(dB0, aF0[2], cB1.x, cB1.y);
            mma_acc(dA1, aF1[2], cA1.x, cA1.y);
            mma_acc(dB1, aF1[2], cB1.x, cB1.y);
            mma_acc(dA0, aF0[3], cA1.z, cA1.w);
            mma_acc(dB0, aF0[3], cB1.z, cB1.w);
            mma_acc(dA1, aF1[3], cA1.z, cA1.w);
            mma_acc(dB1, aF1[3], cB1.z, cB1.w);

            float hv0 = h_s[i * 128 + r0];
            float hv1 = h_s[i * 128 + r0 + 8];
            float hv2 = h_s[i * 128 + r2];
            float hv3 = h_s[i * 128 + r2 + 8];
            float2 bbA = *(const float2*)&b2_s[i * OUT + bcA];
            float2 bbB = *(const float2*)&b2_s[i * OUT + bcB];

            acA0[0] += hv0 * leaky(dA0[0] + bbA.x);
            acA0[1] += hv0 * leaky(dA0[1] + bbA.y);
            acA0[2] += hv1 * leaky(dA0[2] + bbA.x);
            acA0[3] += hv1 * leaky(dA0[3] + bbA.y);
            acB0[0] += hv0 * leaky(dB0[0] + bbB.x);
            acB0[1] += hv0 * leaky(dB0[1] + bbB.y);
            acB0[2] += hv1 * leaky(dB0[2] + bbB.x);
            acB0[3] += hv1 * leaky(dB0[3] + bbB.y);
            acA1[0] += hv2 * leaky(dA1[0] + bbA.x);
            acA1[1] += hv2 * leaky(dA1[1] + bbA.y);
            acA1[2] += hv3 * leaky(dA1[2] + bbA.x);
            acA1[3] += hv3 * leaky(dA1[3] + bbA.y);
            acB1[0] += hv2 * leaky(dB1[0] + bbB.x);
            acB1[1] += hv2 * leaky(dB1[1] + bbB.y);
            acB1[2] += hv3 * leaky(dB1[2] + bbB.x);
            acB1[3] += hv3 * leaky(dB1[3] + bbB.y);

            cA0 = nA0; cA1 = nA1; cB0 = nB0; cB1 = nB1;
        }
        atomicAdd(&agg[d0n * OUT + bcA    ], acA0[0]);
        atomicAdd(&agg[d0n * OUT + bcA + 1], acA0[1]);
        atomicAdd(&agg[d1n * OUT + bcA    ], acA0[2]);
        atomicAdd(&agg[d1n * OUT + bcA + 1], acA0[3]);
        atomicAdd(&agg[d0n * OUT + bcB    ], acB0[0]);
        atomicAdd(&agg[d0n * OUT + bcB + 1], acB0[1]);
        atomicAdd(&agg[d1n * OUT + bcB    ], acB0[2]);
        atomicAdd(&agg[d1n * OUT + bcB + 1], acB0[3]);
        atomicAdd(&agg[d2n * OUT + bcA    ], acA1[0]);
        atomicAdd(&agg[d2n * OUT + bcA + 1], acA1[1]);
        atomicAdd(&agg[d3n * OUT + bcA    ], acA1[2]);
        atomicAdd(&agg[d3n * OUT + bcA + 1], acA1[3]);
        atomicAdd(&agg[d2n * OUT + bcB    ], acB1[0]);
        atomicAdd(&agg[d2n * OUT + bcB + 1], acB1[1]);
        atomicAdd(&agg[d3n * OUT + bcB    ], acB1[2]);
        atomicAdd(&agg[d3n * OUT + bcB + 1], acB1[3]);
    }
}

// ---------------- layer-1 via bf16 mma (IN=4, OUT=8) ------------------------
__global__ __launch_bounds__(128)
void edge_conv1_mma(const float* __restrict__ x,
                    const int*   __restrict__ ei,
                    const float* __restrict__ w1,
                    const float* __restrict__ b1,
                    const uint4* __restrict__ bfrag,
                    const float* __restrict__ b2,
                    float*       __restrict__ agg)
{
    __shared__ uint32_t e_hi[128 * 33];
    __shared__ float h_s[4 * 128];
    __shared__ float attr_s[128 * 3];
    __shared__ float b2s[32];
    __shared__ int   src_s[128], dst_s[128];

    const int tid = threadIdx.x;
    const int e0  = blockIdx.x * 128;

    {
        int j = tid;
        int s = ei[e0 + j];
        int d = ei[N_EDGES + e0 + j];
        src_s[j] = s; dst_s[j] = d;
        attr_s[j * 3 + 0] = x[d * 4 + 1] - x[s * 4 + 1];
        attr_s[j * 3 + 1] = x[d * 4 + 2] - x[s * 4 + 2];
        attr_s[j * 3 + 2] = x[d * 4 + 3] - x[s * 4 + 3];
        float4 hx = *(const float4*)&x[s * 4];
        h_s[0 * 128 + j] = hx.x;
        h_s[1 * 128 + j] = hx.y;
        h_s[2 * 128 + j] = hx.z;
        h_s[3 * 128 + j] = hx.w;
    }
    if (tid < 32) b2s[tid] = b2[tid];
    __syncthreads();

    for (int idx = tid; idx < 4096; idx += 128) {
        int row = idx >> 5, cp = idx & 31;
        float a0 = attr_s[row * 3], a1 = attr_s[row * 3 + 1], a2 = attr_s[row * 3 + 2];
        int c0 = cp * 2, c1 = c0 + 1;
        float v0 = leaky(b1[c0] + a0 * w1[c0] + a1 * w1[64 + c0] + a2 * w1[128 + c0]);
        float v1 = leaky(b1[c1] + a0 * w1[c1] + a1 * w1[64 + c1] + a2 * w1[128 + c1]);
        e_hi[row * 33 + cp] = pack_bf2(v0, v1);
    }
    __syncthreads();

    const int lane = tid & 31, w = tid >> 5;
    const int g = lane >> 2, t4 = lane & 3;
    const int r0 = w * 32 + g;
    const int r2 = r0 + 16;

    uint32_t aF0[4][4], aF1[4][4];
#pragma unroll
    for (int kt = 0; kt < 4; kt++) {
        int cp = kt * 8 + t4;
        aF0[kt][0] = e_hi[(r0    ) * 33 + cp];
        aF0[kt][1] = e_hi[(r0 + 8) * 33 + cp];
        aF0[kt][2] = e_hi[(r0    ) * 33 + cp + 4];
        aF0[kt][3] = e_hi[(r0 + 8) * 33 + cp + 4];
        aF1[kt][0] = e_hi[(r2    ) * 33 + cp];
        aF1[kt][1] = e_hi[(r2 + 8) * 33 + cp];
        aF1[kt][2] = e_hi[(r2    ) * 33 + cp + 4];
        aF1[kt][3] = e_hi[(r2 + 8) * 33 + cp + 4];
    }

    float acc0[4] = {0,0,0,0}, acc1[4] = {0,0,0,0};

#pragma unroll
    for (int og = 0; og < 4; og++) {
        uint4 bq0 = bfrag[(og * 32 + lane) * 2];
        uint4 bq1 = bfrag[(og * 32 + lane) * 2 + 1];
        float2 bb = *(const float2*)&b2s[og * 8 + t4 * 2];
        float d0[4] = {0,0,0,0};
        float d1[4] = {0,0,0,0};
        mma_acc(d0, aF0[0], bq0.x, bq0.y);
        mma_acc(d1, aF1[0], bq0.x, bq0.y);
        mma_acc(d0, aF0[1], bq0.z, bq0.w);
        mma_acc(d1, aF1[1], bq0.z, bq0.w);
        mma_acc(d0, aF0[2], bq1.x, bq1.y);
        mma_acc(d1, aF1[2], bq1.x, bq1.y);
        mma_acc(d0, aF0[3], bq1.z, bq1.w);
        mma_acc(d1, aF1[3], bq1.z, bq1.w);

        float hv0 = h_s[og * 128 + r0];
        float hv1 = h_s[og * 128 + r0 + 8];
        float hv2 = h_s[og * 128 + r2];
        float hv3 = h_s[og * 128 + r2 + 8];
        acc0[0] += hv0 * leaky(d0[0] + bb.x);
        acc0[1] += hv0 * leaky(d0[1] + bb.y);
        acc0[2] += hv1 * leaky(d0[2] + bb.x);
        acc0[3] += hv1 * leaky(d0[3] + bb.y);
        acc1[0] += hv2 * leaky(d1[0] + bb.x);
        acc1[1] += hv2 * leaky(d1[1] + bb.y);
        acc1[2] += hv3 * leaky(d1[2] + bb.x);
        acc1[3] += hv3 * leaky(d1[3] + bb.y);
    }

    const int bo = t4 * 2;
    atomicAdd(&agg[dst_s[r0     ] * 8 + bo    ], acc0[0]);
    atomicAdd(&agg[dst_s[r0     ] * 8 + bo + 1], acc0[1]);
    atomicAdd(&agg[dst_s[r0 +  8] * 8 + bo    ], acc0[2]);
    atomicAdd(&agg[dst_s[r0 +  8] * 8 + bo + 1], acc0[3]);
    atomicAdd(&agg[dst_s[r2     ] * 8 + bo    ], acc1[0]);
    atomicAdd(&agg[dst_s[r2     ] * 8 + bo + 1], acc1[1]);
    atomicAdd(&agg[dst_s[r2 +  8] * 8 + bo    ], acc1[2]);
    atomicAdd(&agg[dst_s[r2 +  8] * 8 + bo + 1], acc1[3]);
}

// ---------------- node update: h_next = leaky(agg + h @ root + cb) ---------
__global__ void node_update_kernel(const float* __restrict__ h,
                                   const float* __restrict__ agg,
                                   const float* __restrict__ root,
                                   const float* __restrict__ cb,
                                   float* __restrict__ out,
                                   int IN, int OUT)
{
    int gid = blockIdx.x * blockDim.x + threadIdx.x;
    if (gid >= N_NODES * OUT) return;
    int n = gid / OUT, o = gid % OUT;
    float t = agg[gid] + cb[o];
    for (int i = 0; i < IN; i++) t += h[n * IN + i] * root[i * OUT + o];
    out[gid] = leaky(t);
}

// ---------------- fused node_update3 + sum-pool ------------------------------
// h3[n] = leaky(agg3[n] + h2[n]@root3 + cb3) computed on the fly and pooled.
#define POOL_CHUNK 50
__global__ __launch_bounds__(128)
void pool_fused_kernel(const float* __restrict__ agg3,
                       const float* __restrict__ h2,
                       const float* __restrict__ root3,
                       const float* __restrict__ cb3,
                       const int*   __restrict__ batch,
                       float*       __restrict__ g)
{
    __shared__ float r3s[64 * 128];          // 32 KB: whole root3
    __shared__ float h2s[POOL_CHUNK * 64];   // 12.8 KB: h2 rows for this chunk

    const int o  = threadIdx.x;              // 128 threads
    const int n0 = blockIdx.x * POOL_CHUNK;
    int n1 = n0 + POOL_CHUNK; if (n1 > N_NODES) n1 = N_NODES;
    const int cnt = n1 - n0;

    for (int idx = o; idx < 2048; idx += 128)
        ((float4*)r3s)[idx] = ((const float4*)root3)[idx];
    for (int idx = o; idx < cnt * 16; idx += 128)
        ((float4*)h2s)[idx] = ((const float4*)(h2 + n0 * 64))[idx];
    __syncthreads();

    const float cbv = cb3[o];
    float s = 0.f;
    int cur = batch[n0];
    for (int n = n0; n < n1; n++) {
        int b = batch[n];
        if (b != cur) { atomicAdd(&g[cur * 128 + o], s); s = 0.f; cur = b; }
        float t = agg3[n * 128 + o] + cbv;
        const float* hr = h2s + (n - n0) * 64;
#pragma unroll 4
        for (int i = 0; i < 64; i++) t += hr[i] * r3s[i * 128 + o];
        s += leaky(t);
    }
    atomicAdd(&g[cur * 128 + o], s);
}

// ---------------- readout MLP: 128->128->64->1 ------------------------------
__global__ void readout_kernel(const float* __restrict__ g,
                               const float* __restrict__ w1, const float* __restrict__ b1,
                               const float* __restrict__ w2, const float* __restrict__ b2,
                               const float* __restrict__ w3, const float* __restrict__ b3,
                               float* __restrict__ out)
{
    __shared__ float gin[128], g1[128], g2[64];
    int b = blockIdx.x, t = threadIdx.x;
    gin[t] = g[b * 128 + t];
    __syncthreads();
    float s = b1[t];
    for (int i = 0; i < 128; i++) s += gin[i] * w1[i * 128 + t];
    g1[t] = leaky(s);
    __syncthreads();
    if (t < 64) {
        float s2 = b2[t];
        for (int i = 0; i < 128; i++) s2 += g1[i] * w2[i * 64 + t];
        g2[t] = leaky(s2);
    }
    __syncthreads();
    if (t < 64) g1[t] = g2[t] * w3[t];
    __syncthreads();
    if (t == 0) {
        float s3 = b3[0];
        for (int i = 0; i < 64; i++) s3 += g1[i];
        out[b] = s3;
    }
}

// ---------------- launch ----------------------------------------------------
static constexpr int smem_mma(int IN, int OUT) {
    return 4 * (128 * 33 + IN * 128 + IN * OUT + 384 + 256);
}

extern "C" void kernel_launch(void* const* d_in, const int* in_sizes, int n_in,
                              void* d_out, int out_size)
{
    const float* x       = (const float*)d_in[0];
    const int*   ei      = (const int*)  d_in[1];
    const int*   batch   = (const int*)  d_in[2];
    const float* en1_w1  = (const float*)d_in[3];
    const float* en1_b1  = (const float*)d_in[4];
    const float* en1_w2  = (const float*)d_in[5];
    const float* en1_b2  = (const float*)d_in[6];
    const float* en2_w1  = (const float*)d_in[7];
    const float* en2_b1  = (const float*)d_in[8];
    const float* en2_w2  = (const float*)d_in[9];
    const float* en2_b2  = (const float*)d_in[10];
    const float* en3_w1  = (const float*)d_in[11];
    const float* en3_b1  = (const float*)d_in[12];
    const float* en3_w2  = (const float*)d_in[13];
    const float* en3_b2  = (const float*)d_in[14];
    const float* root1   = (const float*)d_in[15];
    const float* cb1     = (const float*)d_in[16];
    const float* root2   = (const float*)d_in[17];
    const float* cb2     = (const float*)d_in[18];
    const float* root3   = (const float*)d_in[19];
    const float* cb3     = (const float*)d_in[20];
    const float* fc1_w   = (const float*)d_in[21];
    const float* fc1_b   = (const float*)d_in[22];
    const float* fc2_w   = (const float*)d_in[23];
    const float* fc2_b   = (const float*)d_in[24];
    const float* fc3_w   = (const float*)d_in[25];
    const float* fc3_b   = (const float*)d_in[26];

    float *h1, *h2, *aggz;
    uint4 *bf3, *bf2, *bf1;
    cudaGetSymbolAddress((void**)&h1,   g_h1);
    cudaGetSymbolAddress((void**)&h2,   g_h2);
    cudaGetSymbolAddress((void**)&aggz, g_aggz);
    cudaGetSymbolAddress((void**)&bf3,  g_bf_l3);
    cudaGetSymbolAddress((void**)&bf2,  g_bf_l2);
    cudaGetSymbolAddress((void**)&bf1,  g_bf_l1);

    float* agg1 = aggz;                    // N*8
    float* agg2 = aggz + N_NODES * 8;      // N*64
    float* agg3 = aggz + N_NODES * 72;     // N*128
    float* gp   = aggz + N_NODES * 200;    // 32*128

    constexpr int SM2 = smem_mma(8, 64);
    constexpr int SM3 = smem_mma(64, 128);
    cudaFuncSetAttribute(edge_conv_mma<64, 128>,
                         cudaFuncAttributeMaxDynamicSharedMemorySize, SM3);
    cudaFuncSetAttribute(edge_conv_mma<8, 64>,
                         cudaFuncAttributeMaxDynamicSharedMemorySize, SM2);

    // ---- setup: zero accumulators + build all fragments (ONE launch)
    constexpr int NZ4 = (N_NODES * 200 + N_GRAPHS * 128) / 4;
    setup_kernel<<<(NZ4 + 255) / 256, 256>>>((float4*)aggz, NZ4,
                                             en3_w2, bf3, en2_w2, bf2, en1_w2, bf1);

    // ---- layer 1: in=4, out=8 (bf16 mma)
    edge_conv1_mma<<<N_EDGES / 128, 128>>>(x, ei, en1_w1, en1_b1, bf1, en1_b2, agg1);
    node_update_kernel<<<(N_NODES * 8 + 255) / 256, 256>>>(x, agg1, root1, cb1, h1, 4, 8);

    // ---- layer 2: in=8, out=64 (bf16 mma)
    edge_conv_mma<8, 64><<<N_EDGES / 128, 128, SM2>>>(
        x, h1, ei, en2_w1, en2_b1, bf2, en2_b2, agg2);
    node_update_kernel<<<(N_NODES * 64 + 255) / 256, 256>>>(h1, agg2, root2, cb2, h2, 8, 64);

    // ---- layer 3: in=64, out=128 (bf16 mma)
    edge_conv_mma<64, 128><<<N_EDGES / 128, 128, SM3>>>(
        x, h2, ei, en3_w1, en3_b1, bf3, en3_b2, agg3);

    // ---- fused node_update3 + pool, then readout
    pool_fused_kernel<<<(N_NODES + POOL_CHUNK - 1) / POOL_CHUNK, 128>>>(
        agg3, h2, root3, cb3, batch, gp);
    readout_kernel<<<N_GRAPHS, 128>>>(gp, fc1_w, fc1_b, fc2_w, fc2_b, fc3_w, fc3_b,
                                      (float*)d_out);
}

// round 13
// speedup vs baseline: 1.2915x; 1.2915x over previous
#include <cuda_runtime.h>
#include <cuda_bf16.h>
#include <cstdint>

#define N_NODES  8000
#define N_EDGES  32000
#define N_GRAPHS 32

// ---------------- scratch (device globals; no allocations anywhere) --------
__device__ float g_h1[N_NODES * 8];
__device__ float g_h2[N_NODES * 64];
// one contiguous zeroed region: agg1 | agg2 | agg3 | pool
__device__ float g_aggz[N_NODES * 200 + N_GRAPHS * 128];
// bf16 B-fragments of w2, per-lane contiguous layout:
// uint4 index = ((og*IN + i)*32 + lane)*2 + q
__device__ uint4 g_bf_l3[16 * 64 * 32 * 2];
__device__ uint4 g_bf_l2[8 * 8 * 32 * 2];
__device__ uint4 g_bf_l1[4 * 1 * 32 * 2];

__device__ __forceinline__ float leaky(float v) { return fmaxf(v, 0.1f * v); }

__device__ __forceinline__ uint32_t pack_bf2(float x, float y) {
    __nv_bfloat16 bx = __float2bfloat16(x);
    __nv_bfloat16 by = __float2bfloat16(y);
    uint16_t ux = *(uint16_t*)&bx, uy = *(uint16_t*)&by;
    return (uint32_t)ux | ((uint32_t)uy << 16);
}

// mma.sync m16n8k16 row.col f32 += bf16*bf16 (accumulate in place)
__device__ __forceinline__ void mma_acc(float* d, const uint32_t* a,
                                        uint32_t b0, uint32_t b1) {
    asm volatile(
        "mma.sync.aligned.m16n8k16.row.col.f32.bf16.bf16.f32 "
        "{%0,%1,%2,%3}, {%4,%5,%6,%7}, {%8,%9}, {%0,%1,%2,%3};"
        : "+f"(d[0]), "+f"(d[1]), "+f"(d[2]), "+f"(d[3])
        : "r"(a[0]), "r"(a[1]), "r"(a[2]), "r"(a[3]), "r"(b0), "r"(b1));
}

// ---------------- prep body: one uint4 fragment of w2 ----------------------
__device__ __forceinline__ void prep_one(const float* __restrict__ w2,
                                         uint4* __restrict__ frag,
                                         int IN, int OUT, int idx)
{
    int q    = idx & 1;
    int lane = (idx >> 1) & 31;
    int i    = (idx >> 6) % IN;
    int og   = idx / (IN * 64);
    int t4 = lane & 3, g = lane >> 2;
    int ncols = IN * OUT;
    int col = i * OUT + og * 8 + g;

    uint32_t r[4];
#pragma unroll
    for (int kk = 0; kk < 2; kk++) {
        int kt = q * 2 + kk;
        int k0 = kt * 16 + t4 * 2;
        r[kk * 2 + 0] = pack_bf2(w2[(k0    ) * ncols + col], w2[(k0 + 1) * ncols + col]);
        r[kk * 2 + 1] = pack_bf2(w2[(k0 + 8) * ncols + col], w2[(k0 + 9) * ncols + col]);
    }
    frag[idx] = make_uint4(r[0], r[1], r[2], r[3]);
}

// ---------------- setup: zero accumulators + build ALL fragments, 1 launch --
__global__ void setup_kernel(float4* __restrict__ aggz4, int nz4,
                             const float* __restrict__ w2_3, uint4* __restrict__ bf3,
                             const float* __restrict__ w2_2, uint4* __restrict__ bf2,
                             const float* __restrict__ w2_1, uint4* __restrict__ bf1)
{
    int gid = blockIdx.x * blockDim.x + threadIdx.x;
    if (gid < nz4) aggz4[gid] = make_float4(0.f, 0.f, 0.f, 0.f);
    if (gid < 65536) {
        prep_one(w2_3, bf3, 64, 128, gid);
    } else if (gid < 65536 + 4096) {
        prep_one(w2_2, bf2, 8, 64, gid - 65536);
    } else if (gid < 65536 + 4096 + 256) {
        prep_one(w2_1, bf1, 1, 32, gid - 65536 - 4096);
    }
}

// ---------------- fused NNConv via bf16 mma.sync (layers 2 & 3) -------------
// Block = 128 edges, 256 threads = 8 warps. Warps 0-3 handle og-groups
// [0, OG/2), warps 4-7 handle [OG/2, OG); each warp covers all 128 edges
// as TWO M16 tiles (32 edges). Doubles warps/SM vs round 12 to hide the
// MMA latency chains that capped issue at 15%.
template <int IN, int OUT>
__global__ __launch_bounds__(256)
void edge_conv_mma(const float* __restrict__ x,
                   const float* __restrict__ h,
                   const int*   __restrict__ ei,
                   const float* __restrict__ w1,
                   const float* __restrict__ b1,
                   const uint4* __restrict__ bfrag,
                   const float* __restrict__ b2,
                   float*       __restrict__ agg)
{
    constexpr int OG = OUT / 8;
    constexpr int W_EHI  = 0;                    // 128 x 33 bf16x2 words
    constexpr int W_H    = W_EHI + 128 * 33;     // IN x 128 fp32
    constexpr int W_B2   = W_H + IN * 128;       // IN*OUT fp32
    constexpr int W_ATTR = W_B2 + IN * OUT;      // 384
    constexpr int W_SRC  = W_ATTR + 384;
    constexpr int W_DST  = W_SRC + 128;

    extern __shared__ uint32_t sm[];
    uint32_t* e_hi   = sm + W_EHI;
    float*    h_s    = (float*)(sm + W_H);
    float*    b2_s   = (float*)(sm + W_B2);
    float*    attr_s = (float*)(sm + W_ATTR);
    int*      src_s  = (int*)(sm + W_SRC);
    int*      dst_s  = (int*)(sm + W_DST);

    const int tid = threadIdx.x;
    const int e0  = blockIdx.x * 128;

    // --- edge indices + relative-position attrs
    if (tid < 128) {
        int j = tid;
        int s = ei[e0 + j];
        int d = ei[N_EDGES + e0 + j];
        src_s[j] = s; dst_s[j] = d;
        attr_s[j * 3 + 0] = x[d * 4 + 1] - x[s * 4 + 1];
        attr_s[j * 3 + 1] = x[d * 4 + 2] - x[s * 4 + 2];
        attr_s[j * 3 + 2] = x[d * 4 + 3] - x[s * 4 + 3];
    }
    // --- stage b2
    for (int idx = tid; idx < IN * OUT / 4; idx += 256)
        ((float4*)b2_s)[idx] = ((const float4*)b2)[idx];
    __syncthreads();

    // --- edge hidden e = leaky(attr @ w1 + b1), packed bf16x2
    for (int idx = tid; idx < 4096; idx += 256) {
        int row = idx >> 5, cp = idx & 31;
        float a0 = attr_s[row * 3], a1 = attr_s[row * 3 + 1], a2 = attr_s[row * 3 + 2];
        int c0 = cp * 2, c1 = c0 + 1;
        float v0 = leaky(b1[c0] + a0 * w1[c0] + a1 * w1[64 + c0] + a2 * w1[128 + c0]);
        float v1 = leaky(b1[c1] + a0 * w1[c1] + a1 * w1[64 + c1] + a2 * w1[128 + c1]);
        e_hi[row * 33 + cp] = pack_bf2(v0, v1);
    }
    // --- h[src] gathered transposed: h_s[i*128 + j]
    for (int idx = tid; idx < 128 * (IN / 4); idx += 256) {
        int j = idx & 127, q = idx >> 7;
        float4 v = ((const float4*)(h + src_s[j] * IN))[q];
        h_s[(4 * q + 0) * 128 + j] = v.x;
        h_s[(4 * q + 1) * 128 + j] = v.y;
        h_s[(4 * q + 2) * 128 + j] = v.z;
        h_s[(4 * q + 3) * 128 + j] = v.w;
    }
    __syncthreads();

    const int lane = tid & 31, w = tid >> 5;
    const int wi = w & 3;                 // edge-subset index (0..3)
    const int wg = w >> 2;                // og-half index (0..1)
    const int g = lane >> 2, t4 = lane & 3;
    const int r0 = wi * 32 + g;           // tile0 rows: r0, r0+8
    const int r2 = r0 + 16;               // tile1 rows: r2, r2+8

    // --- A fragments for both tiles (built once)
    uint32_t aF0[4][4], aF1[4][4];
#pragma unroll
    for (int kt = 0; kt < 4; kt++) {
        int cp = kt * 8 + t4;
        aF0[kt][0] = e_hi[(r0    ) * 33 + cp];
        aF0[kt][1] = e_hi[(r0 + 8) * 33 + cp];
        aF0[kt][2] = e_hi[(r0    ) * 33 + cp + 4];
        aF0[kt][3] = e_hi[(r0 + 8) * 33 + cp + 4];
        aF1[kt][0] = e_hi[(r2    ) * 33 + cp];
        aF1[kt][1] = e_hi[(r2 + 8) * 33 + cp];
        aF1[kt][2] = e_hi[(r2    ) * 33 + cp + 4];
        aF1[kt][3] = e_hi[(r2 + 8) * 33 + cp + 4];
    }

    const int d0n = dst_s[r0], d1n = dst_s[r0 + 8];
    const int d2n = dst_s[r2], d3n = dst_s[r2 + 8];

    constexpr int OG2_PER_WG = OG / 4;    // og2 iterations per warp-group
    const int og2_0 = wg * OG2_PER_WG;

    for (int og2 = og2_0; og2 < og2_0 + OG2_PER_WG; og2++) {
        const int ogA = og2 * 2, ogB = ogA + 1;
        const uint4* pA = bfrag + ((size_t)(ogA * IN) * 32 + lane) * 2;
        const uint4* pB = bfrag + ((size_t)(ogB * IN) * 32 + lane) * 2;
        const int bcA = ogA * 8 + t4 * 2;
        const int bcB = ogB * 8 + t4 * 2;

        float acA0[4] = {0,0,0,0}, acB0[4] = {0,0,0,0};
        float acA1[4] = {0,0,0,0}, acB1[4] = {0,0,0,0};

        uint4 cA0 = pA[0], cA1 = pA[1];
        uint4 cB0 = pB[0], cB1 = pB[1];

#pragma unroll 2
        for (int i = 0; i < IN; i++) {
            uint4 nA0, nA1, nB0, nB1;
            if (i + 1 < IN) {
                const uint4* qA = pA + (size_t)(i + 1) * 64;
                const uint4* qB = pB + (size_t)(i + 1) * 64;
                nA0 = qA[0]; nA1 = qA[1];
                nB0 = qB[0]; nB1 = qB[1];
            }

            float dA0[4] = {0,0,0,0}, dB0[4] = {0,0,0,0};
            float dA1[4] = {0,0,0,0}, dB1[4] = {0,0,0,0};
            // 4 independent chains of 4, interleaved
            mma_acc(dA0, aF0[0], cA0.x, cA0.y);
            mma_acc(dB0, aF0[0], cB0.x, cB0.y);
            mma_acc(dA1, aF1[0], cA0.x, cA0.y);
            mma_acc(dB1, aF1[0], cB0.x, cB0.y);
            mma_acc(dA0, aF0[1], cA0.z, cA0.w);
            mma_acc(dB0, aF0[1], cB0.z, cB0.w);
            mma_acc(dA1, aF1[1], cA0.z, cA0.w);
            mma_acc(dB1, aF1[1], cB0.z, cB0.w);
            mma_acc(dA0, aF0[2], cA1.x, cA1.y);
            mma_acc(dB0, aF0[2], cB1.x, cB1.y);
            mma_acc(dA1, aF1[2], cA1.x, cA1.y);
            mma_acc(dB1, aF1[2], cB1.x, cB1.y);
            mma_acc(dA0, aF0[3], cA1.z, cA1.w);
            mma_acc(dB0, aF0[3], cB1.z, cB1.w);
            mma_acc(dA1, aF1[3], cA1.z, cA1.w);
            mma_acc(dB1, aF1[3], cB1.z, cB1.w);

            float hv0 = h_s[i * 128 + r0];
            float hv1 = h_s[i * 128 + r0 + 8];
            float hv2 = h_s[i * 128 + r2];
            float hv3 = h_s[i * 128 + r2 + 8];
            float2 bbA = *(const float2*)&b2_s[i * OUT + bcA];
            float2 bbB = *(const float2*)&b2_s[i * OUT + bcB];

            acA0[0] += hv0 * leaky(dA0[0] + bbA.x);
            acA0[1] += hv0 * leaky(dA0[1] + bbA.y);
            acA0[2] += hv1 * leaky(dA0[2] + bbA.x);
            acA0[3] += hv1 * leaky(dA0[3] + bbA.y);
            acB0[0] += hv0 * leaky(dB0[0] + bbB.x);
            acB0[1] += hv0 * leaky(dB0[1] + bbB.y);
            acB0[2] += hv1 * leaky(dB0[2] + bbB.x);
            acB0[3] += hv1 * leaky(dB0[3] + bbB.y);
            acA1[0] += hv2 * leaky(dA1[0] + bbA.x);
            acA1[1] += hv2 * leaky(dA1[1] + bbA.y);
            acA1[2] += hv3 * leaky(dA1[2] + bbA.x);
            acA1[3] += hv3 * leaky(dA1[3] + bbA.y);
            acB1[0] += hv2 * leaky(dB1[0] + bbB.x);
            acB1[1] += hv2 * leaky(dB1[1] + bbB.y);
            acB1[2] += hv3 * leaky(dB1[2] + bbB.x);
            acB1[3] += hv3 * leaky(dB1[3] + bbB.y);

            cA0 = nA0; cA1 = nA1; cB0 = nB0; cB1 = nB1;
        }
        atomicAdd(&agg[d0n * OUT + bcA    ], acA0[0]);
        atomicAdd(&agg[d0n * OUT + bcA + 1], acA0[1]);
        atomicAdd(&agg[d1n * OUT + bcA    ], acA0[2]);
        atomicAdd(&agg[d1n * OUT + bcA + 1], acA0[3]);
        atomicAdd(&agg[d0n * OUT + bcB    ], acB0[0]);
        atomicAdd(&agg[d0n * OUT + bcB + 1], acB0[1]);
        atomicAdd(&agg[d1n * OUT + bcB    ], acB0[2]);
        atomicAdd(&agg[d1n * OUT + bcB + 1], acB0[3]);
        atomicAdd(&agg[d2n * OUT + bcA    ], acA1[0]);
        atomicAdd(&agg[d2n * OUT + bcA + 1], acA1[1]);
        atomicAdd(&agg[d3n * OUT + bcA    ], acA1[2]);
        atomicAdd(&agg[d3n * OUT + bcA + 1], acA1[3]);
        atomicAdd(&agg[d2n * OUT + bcB    ], acB1[0]);
        atomicAdd(&agg[d2n * OUT + bcB + 1], acB1[1]);
        atomicAdd(&agg[d3n * OUT + bcB    ], acB1[2]);
        atomicAdd(&agg[d3n * OUT + bcB + 1], acB1[3]);
    }
}

// ---------------- layer-1 via bf16 mma (IN=4, OUT=8) ------------------------
__global__ __launch_bounds__(128)
void edge_conv1_mma(const float* __restrict__ x,
                    const int*   __restrict__ ei,
                    const float* __restrict__ w1,
                    const float* __restrict__ b1,
                    const uint4* __restrict__ bfrag,
                    const float* __restrict__ b2,
                    float*       __restrict__ agg)
{
    __shared__ uint32_t e_hi[128 * 33];
    __shared__ float h_s[4 * 128];
    __shared__ float attr_s[128 * 3];
    __shared__ float b2s[32];
    __shared__ int   src_s[128], dst_s[128];

    const int tid = threadIdx.x;
    const int e0  = blockIdx.x * 128;

    {
        int j = tid;
        int s = ei[e0 + j];
        int d = ei[N_EDGES + e0 + j];
        src_s[j] = s; dst_s[j] = d;
        attr_s[j * 3 + 0] = x[d * 4 + 1] - x[s * 4 + 1];
        attr_s[j * 3 + 1] = x[d * 4 + 2] - x[s * 4 + 2];
        attr_s[j * 3 + 2] = x[d * 4 + 3] - x[s * 4 + 3];
        float4 hx = *(const float4*)&x[s * 4];
        h_s[0 * 128 + j] = hx.x;
        h_s[1 * 128 + j] = hx.y;
        h_s[2 * 128 + j] = hx.z;
        h_s[3 * 128 + j] = hx.w;
    }
    if (tid < 32) b2s[tid] = b2[tid];
    __syncthreads();

    for (int idx = tid; idx < 4096; idx += 128) {
        int row = idx >> 5, cp = idx & 31;
        float a0 = attr_s[row * 3], a1 = attr_s[row * 3 + 1], a2 = attr_s[row * 3 + 2];
        int c0 = cp * 2, c1 = c0 + 1;
        float v0 = leaky(b1[c0] + a0 * w1[c0] + a1 * w1[64 + c0] + a2 * w1[128 + c0]);
        float v1 = leaky(b1[c1] + a0 * w1[c1] + a1 * w1[64 + c1] + a2 * w1[128 + c1]);
        e_hi[row * 33 + cp] = pack_bf2(v0, v1);
    }
    __syncthreads();

    const int lane = tid & 31, w = tid >> 5;
    const int g = lane >> 2, t4 = lane & 3;
    const int r0 = w * 32 + g;
    const int r2 = r0 + 16;

    uint32_t aF0[4][4], aF1[4][4];
#pragma unroll
    for (int kt = 0; kt < 4; kt++) {
        int cp = kt * 8 + t4;
        aF0[kt][0] = e_hi[(r0    ) * 33 + cp];
        aF0[kt][1] = e_hi[(r0 + 8) * 33 + cp];
        aF0[kt][2] = e_hi[(r0    ) * 33 + cp + 4];
        aF0[kt][3] = e_hi[(r0 + 8) * 33 + cp + 4];
        aF1[kt][0] = e_hi[(r2    ) * 33 + cp];
        aF1[kt][1] = e_hi[(r2 + 8) * 33 + cp];
        aF1[kt][2] = e_hi[(r2    ) * 33 + cp + 4];
        aF1[kt][3] = e_hi[(r2 + 8) * 33 + cp + 4];
    }

    float acc0[4] = {0,0,0,0}, acc1[4] = {0,0,0,0};

#pragma unroll
    for (int og = 0; og < 4; og++) {
        uint4 bq0 = bfrag[(og * 32 + lane) * 2];
        uint4 bq1 = bfrag[(og * 32 + lane) * 2 + 1];
        float2 bb = *(const float2*)&b2s[og * 8 + t4 * 2];
        float d0[4] = {0,0,0,0};
        float d1[4] = {0,0,0,0};
        mma_acc(d0, aF0[0], bq0.x, bq0.y);
        mma_acc(d1, aF1[0], bq0.x, bq0.y);
        mma_acc(d0, aF0[1], bq0.z, bq0.w);
        mma_acc(d1, aF1[1], bq0.z, bq0.w);
        mma_acc(d0, aF0[2], bq1.x, bq1.y);
        mma_acc(d1, aF1[2], bq1.x, bq1.y);
        mma_acc(d0, aF0[3], bq1.z, bq1.w);
        mma_acc(d1, aF1[3], bq1.z, bq1.w);

        float hv0 = h_s[og * 128 + r0];
        float hv1 = h_s[og * 128 + r0 + 8];
        float hv2 = h_s[og * 128 + r2];
        float hv3 = h_s[og * 128 + r2 + 8];
        acc0[0] += hv0 * leaky(d0[0] + bb.x);
        acc0[1] += hv0 * leaky(d0[1] + bb.y);
        acc0[2] += hv1 * leaky(d0[2] + bb.x);
        acc0[3] += hv1 * leaky(d0[3] + bb.y);
        acc1[0] += hv2 * leaky(d1[0] + bb.x);
        acc1[1] += hv2 * leaky(d1[1] + bb.y);
        acc1[2] += hv3 * leaky(d1[2] + bb.x);
        acc1[3] += hv3 * leaky(d1[3] + bb.y);
    }

    const int bo = t4 * 2;
    atomicAdd(&agg[dst_s[r0     ] * 8 + bo    ], acc0[0]);
    atomicAdd(&agg[dst_s[r0     ] * 8 + bo + 1], acc0[1]);
    atomicAdd(&agg[dst_s[r0 +  8] * 8 + bo    ], acc0[2]);
    atomicAdd(&agg[dst_s[r0 +  8] * 8 + bo + 1], acc0[3]);
    atomicAdd(&agg[dst_s[r2     ] * 8 + bo    ], acc1[0]);
    atomicAdd(&agg[dst_s[r2     ] * 8 + bo + 1], acc1[1]);
    atomicAdd(&agg[dst_s[r2 +  8] * 8 + bo    ], acc1[2]);
    atomicAdd(&agg[dst_s[r2 +  8] * 8 + bo + 1], acc1[3]);
}

// ---------------- node update: h_next = leaky(agg + h @ root + cb) ---------
__global__ void node_update_kernel(const float* __restrict__ h,
                                   const float* __restrict__ agg,
                                   const float* __restrict__ root,
                                   const float* __restrict__ cb,
                                   float* __restrict__ out,
                                   int IN, int OUT)
{
    int gid = blockIdx.x * blockDim.x + threadIdx.x;
    if (gid >= N_NODES * OUT) return;
    int n = gid / OUT, o = gid % OUT;
    float t = agg[gid] + cb[o];
    for (int i = 0; i < IN; i++) t += h[n * IN + i] * root[i * OUT + o];
    out[gid] = leaky(t);
}

// ---------------- fused node_update3 + sum-pool ------------------------------
#define POOL_CHUNK 50
__global__ __launch_bounds__(128)
void pool_fused_kernel(const float* __restrict__ agg3,
                       const float* __restrict__ h2,
                       const float* __restrict__ root3,
                       const float* __restrict__ cb3,
                       const int*   __restrict__ batch,
                       float*       __restrict__ g)
{
    __shared__ float r3s[64 * 128];          // 32 KB: whole root3
    __shared__ float h2s[POOL_CHUNK * 64];   // 12.8 KB: h2 rows for this chunk

    const int o  = threadIdx.x;              // 128 threads
    const int n0 = blockIdx.x * POOL_CHUNK;
    int n1 = n0 + POOL_CHUNK; if (n1 > N_NODES) n1 = N_NODES;
    const int cnt = n1 - n0;

    for (int idx = o; idx < 2048; idx += 128)
        ((float4*)r3s)[idx] = ((const float4*)root3)[idx];
    for (int idx = o; idx < cnt * 16; idx += 128)
        ((float4*)h2s)[idx] = ((const float4*)(h2 + n0 * 64))[idx];
    __syncthreads();

    const float cbv = cb3[o];
    float s = 0.f;
    int cur = batch[n0];
    for (int n = n0; n < n1; n++) {
        int b = batch[n];
        if (b != cur) { atomicAdd(&g[cur * 128 + o], s); s = 0.f; cur = b; }
        float t = agg3[n * 128 + o] + cbv;
        const float* hr = h2s + (n - n0) * 64;
#pragma unroll 4
        for (int i = 0; i < 64; i++) t += hr[i] * r3s[i * 128 + o];
        s += leaky(t);
    }
    atomicAdd(&g[cur * 128 + o], s);
}

// ---------------- readout MLP: 128->128->64->1 ------------------------------
__global__ void readout_kernel(const float* __restrict__ g,
                               const float* __restrict__ w1, const float* __restrict__ b1,
                               const float* __restrict__ w2, const float* __restrict__ b2,
                               const float* __restrict__ w3, const float* __restrict__ b3,
                               float* __restrict__ out)
{
    __shared__ float gin[128], g1[128], g2[64];
    int b = blockIdx.x, t = threadIdx.x;
    gin[t] = g[b * 128 + t];
    __syncthreads();
    float s = b1[t];
    for (int i = 0; i < 128; i++) s += gin[i] * w1[i * 128 + t];
    g1[t] = leaky(s);
    __syncthreads();
    if (t < 64) {
        float s2 = b2[t];
        for (int i = 0; i < 128; i++) s2 += g1[i] * w2[i * 64 + t];
        g2[t] = leaky(s2);
    }
    __syncthreads();
    if (t < 64) g1[t] = g2[t] * w3[t];
    __syncthreads();
    if (t == 0) {
        float s3 = b3[0];
        for (int i = 0; i < 64; i++) s3 += g1[i];
        out[b] = s3;
    }
}

// ---------------- launch ----------------------------------------------------
static constexpr int smem_mma(int IN, int OUT) {
    return 4 * (128 * 33 + IN * 128 + IN * OUT + 384 + 256);
}

extern "C" void kernel_launch(void* const* d_in, const int* in_sizes, int n_in,
                              void* d_out, int out_size)
{
    const float* x       = (const float*)d_in[0];
    const int*   ei      = (const int*)  d_in[1];
    const int*   batch   = (const int*)  d_in[2];
    const float* en1_w1  = (const float*)d_in[3];
    const float* en1_b1  = (const float*)d_in[4];
    const float* en1_w2  = (const float*)d_in[5];
    const float* en1_b2  = (const float*)d_in[6];
    const float* en2_w1  = (const float*)d_in[7];
    const float* en2_b1  = (const float*)d_in[8];
    const float* en2_w2  = (const float*)d_in[9];
    const float* en2_b2  = (const float*)d_in[10];
    const float* en3_w1  = (const float*)d_in[11];
    const float* en3_b1  = (const float*)d_in[12];
    const float* en3_w2  = (const float*)d_in[13];
    const float* en3_b2  = (const float*)d_in[14];
    const float* root1   = (const float*)d_in[15];
    const float* cb1     = (const float*)d_in[16];
    const float* root2   = (const float*)d_in[17];
    const float* cb2     = (const float*)d_in[18];
    const float* root3   = (const float*)d_in[19];
    const float* cb3     = (const float*)d_in[20];
    const float* fc1_w   = (const float*)d_in[21];
    const float* fc1_b   = (const float*)d_in[22];
    const float* fc2_w   = (const float*)d_in[23];
    const float* fc2_b   = (const float*)d_in[24];
    const float* fc3_w   = (const float*)d_in[25];
    const float* fc3_b   = (const float*)d_in[26];

    float *h1, *h2, *aggz;
    uint4 *bf3, *bf2, *bf1;
    cudaGetSymbolAddress((void**)&h1,   g_h1);
    cudaGetSymbolAddress((void**)&h2,   g_h2);
    cudaGetSymbolAddress((void**)&aggz, g_aggz);
    cudaGetSymbolAddress((void**)&bf3,  g_bf_l3);
    cudaGetSymbolAddress((void**)&bf2,  g_bf_l2);
    cudaGetSymbolAddress((void**)&bf1,  g_bf_l1);

    float* agg1 = aggz;                    // N*8
    float* agg2 = aggz + N_NODES * 8;      // N*64
    float* agg3 = aggz + N_NODES * 72;     // N*128
    float* gp   = aggz + N_NODES * 200;    // 32*128

    constexpr int SM2 = smem_mma(8, 64);
    constexpr int SM3 = smem_mma(64, 128);
    cudaFuncSetAttribute(edge_conv_mma<64, 128>,
                         cudaFuncAttributeMaxDynamicSharedMemorySize, SM3);
    cudaFuncSetAttribute(edge_conv_mma<8, 64>,
                         cudaFuncAttributeMaxDynamicSharedMemorySize, SM2);

    // ---- setup: zero accumulators + build all fragments (ONE launch)
    constexpr int NZ4 = (N_NODES * 200 + N_GRAPHS * 128) / 4;
    setup_kernel<<<(NZ4 + 255) / 256, 256>>>((float4*)aggz, NZ4,
                                             en3_w2, bf3, en2_w2, bf2, en1_w2, bf1);

    // ---- layer 1: in=4, out=8 (bf16 mma)
    edge_conv1_mma<<<N_EDGES / 128, 128>>>(x, ei, en1_w1, en1_b1, bf1, en1_b2, agg1);
    node_update_kernel<<<(N_NODES * 8 + 255) / 256, 256>>>(x, agg1, root1, cb1, h1, 4, 8);

    // ---- layer 2: in=8, out=64 (bf16 mma, 8 warps, og split)
    edge_conv_mma<8, 64><<<N_EDGES / 128, 256, SM2>>>(
        x, h1, ei, en2_w1, en2_b1, bf2, en2_b2, agg2);
    node_update_kernel<<<(N_NODES * 64 + 255) / 256, 256>>>(h1, agg2, root2, cb2, h2, 8, 64);

    // ---- layer 3: in=64, out=128 (bf16 mma, 8 warps, og split)
    edge_conv_mma<64, 128><<<N_EDGES / 128, 256, SM3>>>(
        x, h2, ei, en3_w1, en3_b1, bf3, en3_b2, agg3);

    // ---- fused node_update3 + pool, then readout
    pool_fused_kernel<<<(N_NODES + POOL_CHUNK - 1) / POOL_CHUNK, 128>>>(
        agg3, h2, root3, cb3, batch, gp);
    readout_kernel<<<N_GRAPHS, 128>>>(gp, fc1_w, fc1_b, fc2_w, fc2_b, fc3_w, fc3_b,
                                      (float*)d_out);
}